// round 17
// baseline (speedup 1.0000x reference)
#include <cuda_runtime.h>

#define NFFT    512
#define HOPSZ   128
#define BATCH   4
#define LSAMP   131072
#define TFRAMES 1025
#define KW      1023
#define NROWS   (BATCH * NFFT)   // 2048
#define LFFT    2048
#define TCH     16
#define NCHUNK  65

// ------------- device scratch (static, no allocs) -------------
__device__ float2 g_Ht[NCHUNK * NROWS * TCH];   // tiled: [chunk][row][16]
__device__ float2 g_B [7 * LFFT];               // conj-input FFT table (scrambled)
__device__ float2 g_B2[7 * LFFT];               // plain-input FFT table (scrambled)
__device__ float2 g_G [NFFT * LFFT];            // spectrum for row n      (scrambled)
__device__ float2 g_G2[NFFT * LFFT];            // spectrum for row 512-n  (scrambled)
__device__ double g_acc;
__device__ unsigned g_ticket;                   // zero-init; reset by last conv block

__device__ __forceinline__ float2 cmul(float2 a, float2 b) {
    return make_float2(a.x * b.x - a.y * b.y, a.x * b.y + a.y * b.x);
}
__device__ __forceinline__ float2 cadd(float2 a, float2 b) { return make_float2(a.x + b.x, a.y + b.y); }
__device__ __forceinline__ float2 csub(float2 a, float2 b) { return make_float2(a.x - b.x, a.y - b.y); }
__device__ __forceinline__ float2 cnegi(float2 a) { return make_float2(a.y, -a.x); }   // -i*a
__device__ __forceinline__ float2 cposi(float2 a) { return make_float2(-a.y, a.x); }   // +i*a

// 8-pt DFT on registers; reg p holds bin binOf[p], binOf={0,4,1,5,2,6,3,7}, posOf={0,2,4,6,1,3,5,7}
__device__ __forceinline__ void fwd8(float2* z) {
    const float r = 0.70710678118654752f;
    const float2 W1 = make_float2(r, -r);
    const float2 W3 = make_float2(-r, -r);
    float2 t0 = cadd(z[0], z[4]), t1 = csub(z[0], z[4]);
    float2 t2 = cadd(z[2], z[6]), u3 = cnegi(csub(z[2], z[6]));
    float2 p0 = cadd(t0, t2), p2 = cadd(t1, u3), p4 = csub(t0, t2), p6 = csub(t1, u3);
    t0 = cadd(z[1], z[5]); t1 = csub(z[1], z[5]);
    t2 = cadd(z[3], z[7]); u3 = cnegi(csub(z[3], z[7]));
    float2 p1 = cadd(t0, t2);
    float2 p3 = cmul(cadd(t1, u3), W1);
    float2 p5 = cnegi(csub(t0, t2));
    float2 p7 = cmul(csub(t1, u3), W3);
    z[0] = cadd(p0, p1); z[1] = csub(p0, p1);
    z[2] = cadd(p2, p3); z[3] = csub(p2, p3);
    z[4] = cadd(p4, p5); z[5] = csub(p4, p5);
    z[6] = cadd(p6, p7); z[7] = csub(p6, p7);
}

// inverse: input in binOf layout, output natural j order (unnormalized x8)
__device__ __forceinline__ void inv8(float2* z) {
    const float r = 0.70710678118654752f;
    const float2 W1c = make_float2(r, r);
    const float2 W3c = make_float2(-r, r);
    float2 q0 = cadd(z[0], z[1]), q1 = csub(z[0], z[1]);
    float2 q2 = cadd(z[2], z[3]), q3 = csub(z[2], z[3]);
    float2 q4 = cadd(z[4], z[5]), q5 = csub(z[4], z[5]);
    float2 q6 = cadd(z[6], z[7]), q7 = csub(z[6], z[7]);
    float2 t0 = cadd(q0, q4), t1 = csub(q0, q4);
    float2 t2 = cadd(q2, q6), v3 = cposi(csub(q2, q6));
    z[0] = cadd(t0, t2); z[2] = cadd(t1, v3); z[4] = csub(t0, t2); z[6] = csub(t1, v3);
    float2 b = cmul(q3, W1c);
    float2 c = cposi(q5);
    float2 d = cmul(q7, W3c);
    t0 = cadd(q1, c); t1 = csub(q1, c);
    t2 = cadd(b, d);  v3 = cposi(csub(b, d));
    z[1] = cadd(t0, t2); z[3] = cadd(t1, v3); z[5] = csub(t0, t2); z[7] = csub(t1, v3);
}

// build w[i] = w1^(i+1), i=0..6, via power tree
__device__ __forceinline__ void make_tw7(float2 w1, float2* w) {
    w[0] = w1;
    w[1] = cmul(w1, w1);
    w[2] = cmul(w[1], w1);
    w[3] = cmul(w[1], w[1]);
    w[4] = cmul(w[2], w[1]);
    w[5] = cmul(w[2], w[2]);
    w[6] = cmul(w[3], w[2]);
}

// apply precomputed powers to regs in binOf layout
__device__ __forceinline__ void twiddle_apply(float2* z, const float2* w) {
    const int posOf[8] = {0, 2, 4, 6, 1, 3, 5, 7};
#pragma unroll
    for (int m = 1; m < 8; m++)
        z[posOf[m]] = cmul(z[posOf[m]], w[m - 1]);
}

// multiply bin m by w1^m (regs in binOf layout); tree internally
__device__ __forceinline__ void twiddle_chain(float2* z, float2 w1) {
    float2 w[7];
    make_tw7(w1, w);
    twiddle_apply(z, w);
}

__device__ __forceinline__ float2 twf(float invden, int j) {
    float s, c;
    sincospif(-(float)j * invden, &s, &c);
    return make_float2(c, s);
}
__device__ __forceinline__ float2 twfc(float invden, int j) {   // conj
    float s, c;
    sincospif((float)j * invden, &s, &c);
    return make_float2(c, s);
}

__device__ __forceinline__ float2 shflx(float2 v, int m) {
    return make_float2(__shfl_xor_sync(0xffffffffu, v.x, m),
                       __shfl_xor_sync(0xffffffffu, v.y, m));
}

// distributed 4-pt DFT across lanes l=j2 (lane&3)
__device__ __forceinline__ void fwd4sh(float2* z, int l) {
#pragma unroll
    for (int p = 0; p < 8; p++) {
        float2 v = z[p];
        float2 q = shflx(v, 2);
        v = (l & 2) ? csub(q, v) : cadd(v, q);
        if (l == 3) v = cnegi(v);
        q = shflx(v, 1);
        v = (l & 1) ? csub(q, v) : cadd(v, q);
        z[p] = v;
    }
}

__device__ __forceinline__ void inv4sh(float2* z, int l) {
#pragma unroll
    for (int p = 0; p < 8; p++) {
        float2 v = z[p];
        float2 q = shflx(v, 1);
        v = (l & 1) ? csub(q, v) : cadd(v, q);
        if (l == 3) v = cposi(v);
        q = shflx(v, 2);
        v = (l & 2) ? csub(q, v) : cadd(v, q);
        z[p] = v;
    }
}

// ---- forward 2048-pt path (8-8-8-4), float2 exchanges, spectrum left in z ----
__device__ __forceinline__ void fft2048_fwd_reg(float2* z, float2* sX1, float2* sX2, int t) {
    const int binOf[8] = {0, 4, 1, 5, 2, 6, 3, 7};
    fwd8(z);
    twiddle_chain(z, twf(1.0f / 1024.0f, t));          // W_2048^t
#pragma unroll
    for (int p = 0; p < 8; p++) sX1[binOf[p] * 256 + t] = z[p];
    __syncthreads();

    int mA = t >> 5, j1 = t & 31;
#pragma unroll
    for (int v = 0; v < 8; v++) z[v] = sX1[mA * 256 + j1 + 32 * v];
    fwd8(z);
    twiddle_chain(z, twf(1.0f / 128.0f, j1));          // W_256^j1
#pragma unroll
    for (int p = 0; p < 8; p++) sX2[(mA * 8 + binOf[p]) * 36 + j1] = z[p];
    __syncthreads();

    int g = t >> 2, j2 = t & 3;
#pragma unroll
    for (int w = 0; w < 8; w++) z[w] = sX2[g * 36 + j2 + 4 * w];
    fwd8(z);
    twiddle_chain(z, twf(1.0f / 16.0f, j2));           // W_32^j2
    fwd4sh(z, j2);
}

// masked last-stage eval: |c|^2 at lags u=0,1,7 (+2 for t<=1, +6 for t>=1)
__device__ __forceinline__ float final_eval(const float2* Y, const float2* w, int t) {
    float2 y0  = Y[t];
    float2 y1  = cmul(Y[256 + t],  w[0]);
    float2 y2v = cmul(Y[512 + t],  w[1]);
    float2 y3  = cmul(Y[768 + t],  w[2]);
    float2 y4  = cmul(Y[1024 + t], w[3]);
    float2 y5  = cmul(Y[1280 + t], w[4]);
    float2 y6v = cmul(Y[1536 + t], w[5]);
    float2 y7  = cmul(Y[1792 + t], w[6]);
    const float r = 0.70710678118654752f;
    float2 P04 = cadd(y0, y4),   M04 = csub(y0, y4);
    float2 P26 = cadd(y2v, y6v), M26 = csub(y2v, y6v);
    float2 T1  = cadd(y1, y5),   S1  = csub(y1, y5);
    float2 T3  = cadd(y3, y7),   S3  = csub(y3, y7);
    float2 x0 = cadd(cadd(P04, P26), cadd(T1, T3));
    float2 sm = csub(S1, S3), sp = cadd(S1, S3);
    float2 a = make_float2(M04.x + r * sm.x, M04.y + r * sm.y);
    float2 b = make_float2(M26.x + r * sp.x, M26.y + r * sp.y);
    float lsum = x0.x * x0.x + x0.y * x0.y
               + 2.0f * (a.x * a.x + a.y * a.y + b.x * b.x + b.y * b.y);
    float2 e = csub(P04, P26);
    float2 f = csub(T1, T3);
    if (t == 0) {
        float2 x2 = make_float2(e.x - f.y, e.y + f.x);
        lsum += x2.x * x2.x + x2.y * x2.y;
    } else if (t == 1) {
        lsum += 2.0f * (e.x * e.x + e.y * e.y + f.x * f.x + f.y * f.y);
    } else {
        float2 x6 = make_float2(e.x + f.y, e.y - f.x);
        lsum += x6.x * x6.x + x6.y * x6.y;
    }
    return lsum;
}

// ---------------- alpha tables: variant 0 -> g_B (conj input), 1 -> g_B2 (plain) ----------------
__global__ __launch_bounds__(256) void alphafft_kernel(const float* __restrict__ ar,
                                                       const float* __restrict__ ai) {
    __shared__ float2 sX1[2048];
    __shared__ float2 sX2[2304];
    int q = blockIdx.x >> 1, var = blockIdx.x & 1, t = threadIdx.x;
    if (blockIdx.x == 0 && t == 0) g_acc = 0.0;

    float sgn = var ? 1.0f : -1.0f;
    float2 z[8];
#pragma unroll
    for (int u = 0; u < 8; u++) {
        int i = t + 256 * u;
        if (u <= 2 || (u == 3 && t < 255))
            z[u] = make_float2(ar[q * KW + i], sgn * ai[q * KW + i]);
        else
            z[u] = make_float2(0.f, 0.f);
    }
    fft2048_fwd_reg(z, sX1, sX2, t);

    float2* __restrict__ out = (var ? g_B2 : g_B) + q * LFFT + t * 8;
#pragma unroll
    for (int p = 0; p < 8; p++)
        out[p] = make_float2(z[p].x, -z[p].y);   // conj
}

// ---------------- G[n,f] and G2[n,f] for n = 0..263 ----------------
#define GN_PER 8
__global__ __launch_bounds__(128) void gcomb_kernel() {
    int f  = blockIdx.x * 128 + threadIdx.x;
    int n0 = blockIdx.y * GN_PER;
    float2 Bq[7], Cq[7], p[7], st[7];
#pragma unroll
    for (int q = 0; q < 7; q++) {
        Bq[q] = g_B [q * LFFT + f];
        Cq[q] = g_B2[q * LFFT + f];
        float qq = (float)(q - 3);
        float s, c;
        sincospif((float)n0 * qq * (1.0f / 256.0f), &s, &c);
        p[q] = make_float2(c, s);
        sincospif(qq * (1.0f / 256.0f), &s, &c);
        st[q] = make_float2(c, s);
    }
    float2* __restrict__ outG  = &g_G [n0 * LFFT + f];
    float2* __restrict__ outG2 = &g_G2[n0 * LFFT + f];
    const float inv = 1.0f / (float)LFFT;
#pragma unroll
    for (int n = 0; n < GN_PER; n++) {
        float gr = 0.f, gi = 0.f, hr = 0.f, hi = 0.f;
#pragma unroll
        for (int q = 0; q < 7; q++) {
            gr += p[q].x * Bq[q].x - p[q].y * Bq[q].y;
            gi += p[q].x * Bq[q].y + p[q].y * Bq[q].x;
            hr += p[q].x * Cq[q].x - p[q].y * Cq[q].y;
            hi += p[q].x * Cq[q].y + p[q].y * Cq[q].x;
        }
        outG [(size_t)n * LFFT] = make_float2(gr * inv, gi * inv);
        outG2[(size_t)n * LFFT] = make_float2(hr * inv, hi * inv);
#pragma unroll
        for (int q = 0; q < 7; q++) p[q] = cmul(p[q], st[q]);
    }
}

// ---------------- STFT: register radix-8, 4 packed FFTs (8 frames) per 256-thread block ----------------
#define WSPAN4 (7 * HOPSZ + NFFT)   // 1408
#define SST    584
__global__ __launch_bounds__(256) void stft_kernel(const float* __restrict__ wav,
                                                   const float* __restrict__ win) {
    __shared__ float sRe[4 * SST];
    __shared__ float sIm[4 * SST];
    __shared__ float sWav[WSPAN4];
    __shared__ float sWin[NFFT];

    int hc  = blockIdx.x;              // half-chunk 0..129
    int b   = blockIdx.y;
    int tid = threadIdx.x;             // 256
    int tf0 = hc * 8;
    int f   = tid >> 6;
    int j   = tid & 63;

    for (int i = tid; i < NFFT; i += 256) sWin[i] = win[i];
    {
        int base = tf0 * HOPSZ - 256;
        const float* __restrict__ wb = wav + b * LSAMP;
#pragma unroll
        for (int k = 0; k < 6; k++) {
            int i = tid + k * 256;
            if (i < WSPAN4) {
                int p = base + i;
                if (p < 0) p = -p;
                if (p >= LSAMP) p = 2 * LSAMP - 2 - p;
                sWav[i] = wb[p];
            }
        }
    }
    __syncthreads();

    float* fRe = &sRe[f * SST];
    float* fIm = &sIm[f * SST];
    float2 z[8];
    const int binOf[8] = {0, 4, 1, 5, 2, 6, 3, 7};

#pragma unroll
    for (int u = 0; u < 8; u++) {
        int i = j + 64 * u;
        float wv = sWin[i];
        z[u] = make_float2(sWav[256 * f + i] * wv, sWav[256 * f + 128 + i] * wv);
    }
    fwd8(z);
    twiddle_chain(z, twf(1.0f / 256.0f, j));           // W_512^j
#pragma unroll
    for (int p = 0; p < 8; p++) {
        fRe[binOf[p] * 72 + j] = z[p].x;
        fIm[binOf[p] * 72 + j] = z[p].y;
    }
    __syncthreads();

    {
        int m = j >> 3, j0 = j & 7;
#pragma unroll
        for (int u = 0; u < 8; u++) {
            int a = m * 72 + j0 + 8 * u;
            z[u] = make_float2(fRe[a], fIm[a]);
        }
        fwd8(z);
        twiddle_chain(z, twf(1.0f / 32.0f, j0));       // W_64^j0
        __syncthreads();
#pragma unroll
        for (int p = 0; p < 8; p++) {
            int a = (m * 8 + binOf[p]) * 9 + j0;
            fRe[a] = z[p].x;
            fIm[a] = z[p].y;
        }
    }
    __syncthreads();

    {
#pragma unroll
        for (int u = 0; u < 8; u++) {
            int a = j * 9 + u;
            z[u] = make_float2(fRe[a], fIm[a]);
        }
        fwd8(z);
        __syncthreads();
        int m = j >> 3, mB = j & 7;
#pragma unroll
        for (int p = 0; p < 8; p++) {
            int n = m + 8 * mB + 64 * binOf[p];
            fRe[n] = z[p].x;
            fIm[n] = z[p].y;
        }
    }
    __syncthreads();

    int chunk = hc >> 1, off8 = (hc & 1) * 8;
#pragma unroll
    for (int k = 0; k < 8; k++) {
        int o = tid + k * 256;             // o = n*4 + p
        int n = o >> 2, p = o & 3;
        int m512 = (NFFT - n) & (NFFT - 1);
        float Znr = sRe[p * SST + n],    Zni = sIm[p * SST + n];
        float Zmr = sRe[p * SST + m512], Zmi = sIm[p * SST + m512];
        int te = tf0 + 2 * p;
        float4 hv;
        if (te <= 1024) {
            hv.x = 0.5f * (Znr + Zmr);  hv.y = 0.5f * (Zni - Zmi);
        } else { hv.x = 0.f; hv.y = 0.f; }
        if (te + 1 <= 1024) {
            hv.z = 0.5f * (Zni + Zmi);  hv.w = -0.5f * (Znr - Zmr);
        } else { hv.z = 0.f; hv.w = 0.f; }
        float4* __restrict__ dst =
            (float4*)&g_Ht[(((size_t)chunk * NROWS + b * NFFT + n) << 4) + off8 + 2 * p];
        *dst = hv;
    }
}

// ---------------- conv: conjugate-pair rows, interleaved dual inverse, fused finalize ----------------
#define CONV_BLOCKS (257 * BATCH)
__global__ __launch_bounds__(256, 3) void conv_kernel(float* __restrict__ out) {
    // pool regions (float2):
    //   sA  = [0,2048)      fwd stage-A / spectrum stash S / Y1
    //   sB  = [2048,4352)   fwd stage-B = inv X1 (self-addressed) / Y2 at [2048,4096)
    //   X2  = [4352,6656)   inv z2 C' output
    __shared__ float2 pool[6656];
    __shared__ float warpsum[8];
    float2* sA = pool;
    float2* sB = pool + 2048;
    float2* X2 = pool + 4352;

    int n   = blockIdx.x;              // 0..256
    int b   = blockIdx.y;
    int row = b * NFFT + n;
    int t   = threadIdx.x;
    bool dual = (n != 0) && (n != 256);

    const int posOf[8] = {0, 2, 4, 6, 1, 3, 5, 7};
    int g  = t >> 2, j2 = t & 3;
    int mA = t >> 5, j1 = t & 31;

    float2 z[8];
#pragma unroll
    for (int u = 0; u < 4; u++) {
        int i = t + 256 * u;
        z[u] = g_Ht[(((i >> 4) * NROWS + row) << 4) + (i & 15)];
    }
    z[4] = (t == 0) ? g_Ht[((64 * NROWS + row) << 4)] : make_float2(0.f, 0.f);
    z[5] = make_float2(0.f, 0.f);
    z[6] = make_float2(0.f, 0.f);
    z[7] = make_float2(0.f, 0.f);

    fft2048_fwd_reg(z, sA, sB, t);     // spectrum in z; sA dead, sB holds fwd-C data (self-addr)

    // stash spectrum into sA (conflict-free p*256+t)
    if (dual) {
#pragma unroll
        for (int p = 0; p < 8; p++) sA[p * 256 + t] = z[p];
    }

    // shared C' twiddle tree
    float2 wC[7];
    make_tw7(twfc(1.0f / 16.0f, j2), wC);

    // z1 = X*G, inverse C' -> X1 (= sB region, same per-thread addresses as fwd-C reads)
    {
        const float4* __restrict__ Gr = (const float4*)&g_G[(size_t)n * LFFT + t * 8];
#pragma unroll
        for (int cc = 0; cc < 4; cc++) {
            float4 gg = Gr[cc];
            float2 x0 = z[2 * cc], x1 = z[2 * cc + 1];
            z[2 * cc]     = make_float2(x0.x * gg.x - x0.y * gg.y, x0.x * gg.y + x0.y * gg.x);
            z[2 * cc + 1] = make_float2(x1.x * gg.z - x1.y * gg.w, x1.x * gg.w + x1.y * gg.z);
        }
    }
    inv4sh(z, j2);
    twiddle_apply(z, wC);
    inv8(z);
#pragma unroll
    for (int w = 0; w < 8; w++) sB[g * 36 + j2 + 4 * w] = z[w];

    // z2 = X*G2, inverse C' -> X2 (virgin region)
    if (dual) {
#pragma unroll
        for (int p = 0; p < 8; p++) z[p] = sA[p * 256 + t];
        const float4* __restrict__ G2r = (const float4*)&g_G2[(size_t)n * LFFT + t * 8];
#pragma unroll
        for (int cc = 0; cc < 4; cc++) {
            float4 gg = G2r[cc];
            float2 x0 = z[2 * cc], x1 = z[2 * cc + 1];
            z[2 * cc]     = make_float2(x0.x * gg.x - x0.y * gg.y, x0.x * gg.y + x0.y * gg.x);
            z[2 * cc + 1] = make_float2(x1.x * gg.z - x1.y * gg.w, x1.x * gg.w + x1.y * gg.z);
        }
        inv4sh(z, j2);
        twiddle_apply(z, wC);
        inv8(z);
#pragma unroll
        for (int w = 0; w < 8; w++) X2[g * 36 + j2 + 4 * w] = z[w];
    }
    __syncthreads();

    // shared B' twiddle tree (alive across midbar)
    float2 wB[7];
    make_tw7(twfc(1.0f / 128.0f, j1), wB);

    // B' for z1: X1 -> Y1 (= sA region; disjoint from X1/X2 reads)
#pragma unroll
    for (int mB = 0; mB < 8; mB++)
        z[posOf[mB]] = sB[(mA * 8 + mB) * 36 + j1];
    twiddle_apply(z, wB);
    inv8(z);
#pragma unroll
    for (int v = 0; v < 8; v++) sA[mA * 256 + j1 + 32 * v] = z[v];
    __syncthreads();   // all X1 reads done -> sB region reusable as Y2

    // B' for z2: X2 -> Y2 (= sB[0,2048) region)
    if (dual) {
#pragma unroll
        for (int mB = 0; mB < 8; mB++)
            z[posOf[mB]] = X2[(mA * 8 + mB) * 36 + j1];
        twiddle_apply(z, wB);
        inv8(z);
#pragma unroll
        for (int v = 0; v < 8; v++) sB[mA * 256 + j1 + 32 * v] = z[v];
    }
    __syncthreads();

    // final masked eval, shared twiddle tree
    float2 wF[7];
    make_tw7(twfc(1.0f / 1024.0f, t), wF);
    float lsum = final_eval(sA, wF, t);
    if (dual) lsum += final_eval(sB, wF, t);

#pragma unroll
    for (int off = 16; off > 0; off >>= 1)
        lsum += __shfl_down_sync(0xffffffff, lsum, off);
    if ((t & 31) == 0) warpsum[t >> 5] = lsum;
    __syncthreads();
    if (t == 0) {
        float s = 0.f;
#pragma unroll
        for (int w = 0; w < 8; w++) s += warpsum[w];
        atomicAdd(&g_acc, (double)s);
        __threadfence();
        unsigned old = atomicAdd(&g_ticket, 1u);
        if (old == (unsigned)(CONV_BLOCKS - 1)) {
            double v = atomicAdd(&g_acc, 0.0);
            out[0] = (float)(v / (double)(BATCH * TFRAMES));
            g_ticket = 0;                 // reset for next graph replay
        }
    }
}

extern "C" void kernel_launch(void* const* d_in, const int* in_sizes, int n_in,
                              void* d_out, int out_size) {
    const float* wav = (const float*)d_in[0];
    const float* win = (const float*)d_in[1];
    const float* ar  = (const float*)d_in[2];
    const float* ai  = (const float*)d_in[3];

    alphafft_kernel<<<14, 256>>>(ar, ai);
    dim3 gG(LFFT / 128, 33);                 // n = 0..263 (covers 0..256 needed)
    gcomb_kernel<<<gG, 128>>>();
    dim3 gs(2 * NCHUNK, BATCH);
    stft_kernel<<<gs, 256>>>(wav, win);
    dim3 gc(257, BATCH);
    conv_kernel<<<gc, 256>>>((float*)d_out);
}